// round 7
// baseline (speedup 1.0000x reference)
#include <cuda_runtime.h>

// Problem constants
#define BB    8
#define CCH   96          // channels
#define TT    1000
#define FF    64
#define LL    12          // layers
#define NCOL  512         // B*F columns
#define PP    12          // CTAs per layer
#define NT    384         // threads per CTA (96 c-lanes x 4 col-groups)
#define DD    4           // state ring depth
#define WW    48          // padded cols per CTA (max M = 43), 12 per thread-group
#define WH    50          // padded cols + 2 halo
#define EPSF  1e-6f

// ---------------- scratch (static device globals; no runtime alloc) -------
__device__ float g_hbuf[LL * DD * CCH * NCOL];   // state/output ring, ~9.4 MB
__device__ float g_xwT[LL * CCH * 288];          // transposed xproj_w  [l][cin][o]
__device__ float g_pwT[LL * CCH * 288];          // transposed hproj_w
__device__ int   g_done[LL];                     // per-layer CTA-step completion count

// smem layout (floats)
#define OFF_Y   0                      // raw y            96*48
#define OFF_YN  4608                   // normed y / s     96*48
#define OFF_HP  9216                   // hp with halo     96*50
#define OFF_HC  14016                  // conv(h-norm)+b   96*48
#define OFF_RY  18624                  // rstd of y cols   48
#define OFF_RH  18672                  // rstd of hp cols  50
#define OFF_RO  18722                  // rstd of out cols 48
#define OFF_INW 18770                  // 96
#define OFF_HNW 18866                  // 96
#define OFF_ONW 18962                  // 96
#define OFF_XB  19058                  // 288
#define OFF_PB  19346                  // 288
#define OFF_HW  19634                  // 3*96 (hw[k][c])
#define OFF_HB  19922                  // 96
#define SMEM_FLOATS 20018
#define SMEM_BYTES  (SMEM_FLOATS * 4)

typedef unsigned long long u64;

__device__ __forceinline__ u64 fma2(u64 a, u64 b, u64 c) {
    u64 d;
    asm("fma.rn.f32x2 %0, %1, %2, %3;" : "=l"(d) : "l"(a), "l"(b), "l"(c));
    return d;
}
__device__ __forceinline__ u64 pack2(float x) {
    u64 d; asm("mov.b64 %0, {%1, %1};" : "=l"(d) : "f"(x)); return d;
}
__device__ __forceinline__ float2 unpack2(u64 v) {
    float2 r; asm("mov.b64 {%0, %1}, %2;" : "=f"(r.x), "=f"(r.y) : "l"(v)); return r;
}

// ---------------- init: reset counters, zero t=-1 state slot, transpose W --
__global__ void gru_init(const float* __restrict__ xw, const float* __restrict__ pw) {
    int idx = blockIdx.x * blockDim.x + threadIdx.x;
    int stride = gridDim.x * blockDim.x;
    if (idx < LL) g_done[idx] = 0;
    const int SLOT = CCH * NCOL;
    for (int i = idx; i < LL * SLOT; i += stride) {
        int l = i / SLOT, r = i - l * SLOT;
        g_hbuf[(l * DD + (DD - 1)) * SLOT + r] = 0.f;   // h at t=-1 is zero
    }
    const int WSZ = 288 * CCH;
    for (int i = idx; i < LL * WSZ; i += stride) {
        int l = i / WSZ, r = i - l * WSZ;
        int o = r / CCH, ci = r - o * CCH;
        g_xwT[l * WSZ + ci * 288 + o] = xw[i];
        g_pwT[l * WSZ + ci * 288 + o] = pw[i];
    }
}

__device__ __forceinline__ int ld_vol(const int* p) {
    int v;
    asm volatile("ld.volatile.global.b32 %0, [%1];" : "=r"(v) : "l"(p) : "memory");
    return v;
}

__device__ __forceinline__ void spin_ge(const int* p, int tgt) {
    while (ld_vol(p) < tgt) {
#if __CUDA_ARCH__ >= 700
        __nanosleep(64);
#endif
    }
}

// ---------------- main persistent wavefront kernel -------------------------
__global__ void __launch_bounds__(NT, 1) gru_main(
    const float* __restrict__ x,
    const float* __restrict__ inw_g,  const float* __restrict__ hnw_g,
    const float* __restrict__ xpb_g,
    const float* __restrict__ hw_g,   const float* __restrict__ hb_g,
    const float* __restrict__ hpb_g,  const float* __restrict__ onw_g,
    float* __restrict__ out)
{
    extern __shared__ float sm[];
    const int tid  = threadIdx.x;
    const int l    = blockIdx.x / PP;
    const int part = blockIdx.x % PP;
    const int n0 = (part * NCOL) / PP;
    const int n1 = ((part + 1) * NCOL) / PP;
    const int M  = n1 - n0;                    // 42 or 43

    // layer params -> smem (persist for whole kernel)
    for (int i = tid; i < CCH; i += NT) {
        sm[OFF_INW + i] = inw_g[l * CCH + i];
        sm[OFF_HNW + i] = hnw_g[l * CCH + i];
        sm[OFF_ONW + i] = onw_g[l * CCH + i];
        sm[OFF_HB  + i] = hb_g [l * CCH + i];
        sm[OFF_HW        + i] = hw_g[(l * CCH + i) * 3 + 0];
        sm[OFF_HW +  96  + i] = hw_g[(l * CCH + i) * 3 + 1];
        sm[OFF_HW + 192  + i] = hw_g[(l * CCH + i) * 3 + 2];
    }
    for (int i = tid; i < 288; i += NT) {
        sm[OFF_XB + i] = xpb_g[l * 288 + i];
        sm[OFF_PB + i] = hpb_g[l * 288 + i];
    }
    __syncthreads();

    const int SLOT = CCH * NCOL;
    const float* __restrict__ xwT = g_xwT + l * (CCH * 288);
    const float* __restrict__ pwT = g_pwT + l * (CCH * 288);
    float* hbl = g_hbuf + l * (DD * SLOT);

    const int c  = tid % CCH;        // channel lane (0..95)
    const int q  = tid / CCH;        // column group (0..3)
    const int mb = q * 12;           // first owned column (12 per thread)
    const int wid  = tid >> 5;
    const int lane = tid & 31;

    const float xb0 = sm[OFF_XB + c], xb1 = sm[OFF_XB + 96 + c], xb2 = sm[OFF_XB + 192 + c];
    const float pb0 = sm[OFF_PB + c], pb1 = sm[OFF_PB + 96 + c], pb2 = sm[OFF_PB + 192 + c];

    #pragma unroll 1
    for (int t = 0; t < TT; ++t) {
        // ---- dependency spin (thread 0 only); fence also invalidates L1D ----
        if (tid == 0) {
            spin_ge(&g_done[l], t * PP);                           // siblings done t-1
            if (l > 0)      spin_ge(&g_done[l - 1], (t + 1) * PP); // input y ready
            if (l < LL - 1) {
                int tgt = (t - DD + 1) * PP;                       // ring slot t%DD free
                if (tgt > 0) spin_ge(&g_done[l + 1], tgt);
            }
            __threadfence();
        }
        __syncthreads();

        const float* hprev = hbl + ((t + DD - 1) % DD) * SLOT;

        // ---- Phase A: load y tile and hp (with halo) to smem ----
        if (l == 0) {
            for (int idx = tid; idx < CCH * WW; idx += NT) {
                int cc = idx / WW, m = idx - cc * WW;
                float v = 0.f;
                if (m < M) {
                    int n = n0 + m, b = n >> 6, f = n & 63;
                    v = x[((b * CCH + cc) * TT + t) * FF + f];
                }
                sm[OFF_Y + idx] = v;
            }
        } else {
            const float* ysrc = g_hbuf + (l - 1) * (DD * SLOT) + (t % DD) * SLOT;
            for (int idx = tid; idx < CCH * WW; idx += NT) {
                int cc = idx / WW, m = idx - cc * WW;
                sm[OFF_Y + idx] = (m < M) ? ysrc[cc * NCOL + n0 + m] : 0.f;
            }
        }
        for (int idx = tid; idx < CCH * WH; idx += NT) {
            int cc = idx / WH, j = idx - cc * WH;
            int n = n0 - 1 + j;
            float v = 0.f;
            if (j < M + 2 && n >= 0 && n < NCOL) v = hprev[cc * NCOL + n];
            sm[OFF_HP + idx] = v;
        }
        __syncthreads();

        // ---- Phase A2: column RMS stats (y: WW cols, hp: WH cols) ----
        for (int col = wid; col < WW + WH; col += (NT / 32)) {
            float ssum;
            if (col < WW) {
                float a = sm[OFF_Y + lane * WW + col];
                float b = sm[OFF_Y + (lane + 32) * WW + col];
                float d = sm[OFF_Y + (lane + 64) * WW + col];
                ssum = a * a + b * b + d * d;
            } else {
                int j = col - WW;
                float a = sm[OFF_HP + lane * WH + j];
                float b = sm[OFF_HP + (lane + 32) * WH + j];
                float d = sm[OFF_HP + (lane + 64) * WH + j];
                ssum = a * a + b * b + d * d;
            }
            #pragma unroll
            for (int o = 16; o; o >>= 1) ssum += __shfl_xor_sync(0xffffffffu, ssum, o);
            if (lane == 0) {
                float r = rsqrtf(ssum * (1.f / 96.f) + EPSF);
                if (col < WW) sm[OFF_RY + col] = r; else sm[OFF_RH + col - WW] = r;
            }
        }
        __syncthreads();

        // ---- Phase B: yn = rms(y)*inw ; hc = dwconv(rms(hp))*hnw + hb ----
        for (int idx = tid; idx < CCH * WW; idx += NT) {
            int cc = idx / WW, m = idx - cc * WW;
            float yn = 0.f, hc = 0.f;
            if (m < M) {
                yn = sm[OFF_Y + idx] * sm[OFF_RY + m] * sm[OFF_INW + cc];
                int f = (n0 + m) & 63;
                float h0 = sm[OFF_HP + cc * WH + m]     * sm[OFF_RH + m];
                float h1 = sm[OFF_HP + cc * WH + m + 1] * sm[OFF_RH + m + 1];
                float h2 = sm[OFF_HP + cc * WH + m + 2] * sm[OFF_RH + m + 2];
                float acc = h1 * sm[OFF_HW + 96 + cc];
                if (f != 0)  acc += h0 * sm[OFF_HW + cc];
                if (f != 63) acc += h2 * sm[OFF_HW + 192 + cc];
                hc = acc * sm[OFF_HNW + cc] + sm[OFF_HB + cc];
            }
            sm[OFF_YN + idx] = yn;
            sm[OFF_HC + idx] = hc;
        }
        __syncthreads();

        // ---- Phase C: fused dual GEMM, f32x2 packed (6 dots x 6 col-pairs) ----
        u64 aXr[6], aXz[6], aXn[6], aHr[6], aHz[6], aHn[6];
        #pragma unroll
        for (int j = 0; j < 6; ++j) { aXr[j]=0ULL; aXz[j]=0ULL; aXn[j]=0ULL; aHr[j]=0ULL; aHz[j]=0ULL; aHn[j]=0ULL; }

        #pragma unroll 2
        for (int k = 0; k < CCH; ++k) {
            const u64 Wx0 = pack2(__ldg(xwT + k * 288 + c));
            const u64 Wx1 = pack2(__ldg(xwT + k * 288 + 96 + c));
            const u64 Wx2 = pack2(__ldg(xwT + k * 288 + 192 + c));
            const u64 Wp0 = pack2(__ldg(pwT + k * 288 + c));
            const u64 Wp1 = pack2(__ldg(pwT + k * 288 + 96 + c));
            const u64 Wp2 = pack2(__ldg(pwT + k * 288 + 192 + c));
            const u64* ynp = (const u64*)(sm + OFF_YN + k * WW + mb);
            const u64* hcp = (const u64*)(sm + OFF_HC + k * WW + mb);
            #pragma unroll
            for (int j = 0; j < 6; ++j) {
                u64 yv = ynp[j], hv = hcp[j];
                aXr[j] = fma2(Wx0, yv, aXr[j]);
                aXz[j] = fma2(Wx1, yv, aXz[j]);
                aXn[j] = fma2(Wx2, yv, aXn[j]);
                aHr[j] = fma2(Wp0, hv, aHr[j]);
                aHz[j] = fma2(Wp1, hv, aHz[j]);
                aHn[j] = fma2(Wp2, hv, aHn[j]);
            }
        }

        // ---- Phase D: gates, state update, s = h_new + y -> smem ----
        float sv[12];
        #pragma unroll
        for (int jj = 0; jj < 6; ++jj) {
            float2 xr2 = unpack2(aXr[jj]), xz2 = unpack2(aXz[jj]), xn2 = unpack2(aXn[jj]);
            float2 hr2 = unpack2(aHr[jj]), hz2 = unpack2(aHz[jj]), hn2 = unpack2(aHn[jj]);
            #pragma unroll
            for (int s2 = 0; s2 < 2; ++s2) {
                int m = mb + 2 * jj + s2;
                float xr = (s2 ? xr2.y : xr2.x) + xb0;
                float xz = (s2 ? xz2.y : xz2.x) + xb1;
                float xn = (s2 ? xn2.y : xn2.x) + xb2;
                float hr = (s2 ? hr2.y : hr2.x) + pb0;
                float hz = (s2 ? hz2.y : hz2.x) + pb1;
                float hn = (s2 ? hn2.y : hn2.x) + pb2;
                float r = 1.f / (1.f + __expf(-(xr + hr)));
                float z = 1.f / (1.f + __expf(-(xz + hz)));
                float cand = tanhf(xn + r * hn);
                float hp = sm[OFF_HP + c * WH + m + 1];
                float hnew = (1.f - z) * cand + z * hp;
                sv[2 * jj + s2] = hnew + sm[OFF_Y + c * WW + m];
            }
        }
        __syncthreads();  // all GEMM reads of YN done; reuse as s-buffer
        #pragma unroll
        for (int j = 0; j < 12; ++j) {
            int m = mb + j;
            sm[OFF_YN + c * WW + m] = (m < M) ? sv[j] : 0.f;
        }
        __syncthreads();

        // ---- out RMS stats over s columns ----
        for (int col = wid; col < WW; col += (NT / 32)) {
            float a = sm[OFF_YN + lane * WW + col];
            float b = sm[OFF_YN + (lane + 32) * WW + col];
            float d = sm[OFF_YN + (lane + 64) * WW + col];
            float ssum = a * a + b * b + d * d;
            #pragma unroll
            for (int o = 16; o; o >>= 1) ssum += __shfl_xor_sync(0xffffffffu, ssum, o);
            if (lane == 0) sm[OFF_RO + col] = rsqrtf(ssum * (1.f / 96.f) + EPSF);
        }
        __syncthreads();

        // ---- Phase E: out = rms(s)*onw -> state ring (coalesced, m-major) ----
        float* hdst = hbl + (t % DD) * SLOT;
        for (int idx = tid; idx < CCH * WW; idx += NT) {
            int cc = idx / WW, m = idx - cc * WW;
            if (m < M) {
                float v = sm[OFF_YN + idx] * sm[OFF_RO + m] * sm[OFF_ONW + cc];
                int n = n0 + m;
                hdst[cc * NCOL + n] = v;
                if (l == LL - 1) {
                    int b = n >> 6, f = n & 63;
                    out[((b * CCH + cc) * TT + t) * FF + f] = v;
                }
            }
        }
        __threadfence();       // publish hbuf writes gpu-wide
        __syncthreads();
        if (tid == 0) atomicAdd(&g_done[l], 1);
    }
}

// ---------------------------------------------------------------------------
extern "C" void kernel_launch(void* const* d_in, const int* in_sizes, int n_in,
                              void* d_out, int out_size) {
    const float* x    = (const float*)d_in[0];
    const float* inw  = (const float*)d_in[1];
    const float* hnw  = (const float*)d_in[2];
    const float* xpw  = (const float*)d_in[3];
    const float* xpb  = (const float*)d_in[4];
    const float* hmw  = (const float*)d_in[5];
    const float* hmb  = (const float*)d_in[6];
    const float* hpw  = (const float*)d_in[7];
    const float* hpb  = (const float*)d_in[8];
    const float* onw  = (const float*)d_in[9];
    float* out = (float*)d_out;

    cudaFuncSetAttribute(gru_main, cudaFuncAttributeMaxDynamicSharedMemorySize, SMEM_BYTES);

    gru_init<<<256, 256>>>(xpw, hpw);
    gru_main<<<LL * PP, NT, SMEM_BYTES>>>(x, inw, hnw, xpb, hmw, hmb, hpb, onw, out);
}